// round 2
// baseline (speedup 1.0000x reference)
#include <cuda_runtime.h>
#include <math_constants.h>
#include <cstdint>
#include <cstddef>

// ---------------------------------------------------------------------------
// BlocksparseDilatedAttention  (B=2, S=8192, D=768, H=12, hd=64, R=4, SEG=512)
// Stage 1: per-offset QKV projection (gathered SGEMM)      58.0 GFLOP
// Stage 2: 384x segment attention (512x512, hd=64, flash)  25.8 GFLOP
// Stage 3: per-offset output projection + dilated scatter  19.3 GFLOP
// ---------------------------------------------------------------------------

#define BB    2
#define SS    8192
#define DD    768
#define HH    12
#define HD    64
#define RR    4
#define LL    2048          // S / R
#define SEGL  512
#define NSEG  4             // L / SEG
#define MM    4096          // B * L  (rows per offset)
#define QKVN  2304          // 3 * D
#define SCALE 0.125f        // 1/sqrt(64)

// Scratch (allocation-free rule: __device__ globals)
__device__ float g_qkv[(size_t)RR * MM * QKVN];   // 151 MB: [o][m][3D]
__device__ float g_ctx[(size_t)RR * MM * DD];     //  50 MB: [o][m][D]

// ---------------------------------------------------------------------------
// 128x128x16 fp32 SGEMM tile, 256 threads, 8x8 microtile (split 2x 4-wide)
// A rows gathered from x with dilation stride; B = Wqkv[o] (row-major, K
// contiguous). C = A @ B^T + bias -> g_qkv.
// ---------------------------------------------------------------------------
__global__ __launch_bounds__(256, 2)
void qkv_gemm_kernel(const float* __restrict__ x,
                     const float* __restrict__ W,
                     const float* __restrict__ bias)
{
    __shared__ float As[16][128];
    __shared__ float Bs[16][128];

    const int o  = blockIdx.z;
    const int m0 = blockIdx.y * 128;
    const int n0 = blockIdx.x * 128;
    const int t  = threadIdx.x;
    const int ty = t >> 4, tx = t & 15;

    const int lr = t >> 1;      // load row 0..127
    const int kc = t & 1;

    const int am = m0 + lr;
    const int bI = am >> 11;            // batch
    const int l  = am & 2047;           // token within offset
    const float* aptr = x + ((size_t)(bI * SS + l * RR + o)) * DD;
    const float* bptr = W + ((size_t)o * QKVN + (n0 + lr)) * DD;

    float acc[8][8];
#pragma unroll
    for (int i = 0; i < 8; i++)
#pragma unroll
        for (int j = 0; j < 8; j++) acc[i][j] = 0.f;

    for (int kt = 0; kt < DD / 16; kt++) {
        __syncthreads();
#pragma unroll
        for (int u = 0; u < 2; u++) {
            const int k0 = (kc + 2 * u) * 4;
            float4 av = *(const float4*)(aptr + kt * 16 + k0);
            As[k0 + 0][lr] = av.x; As[k0 + 1][lr] = av.y;
            As[k0 + 2][lr] = av.z; As[k0 + 3][lr] = av.w;
            float4 bv = *(const float4*)(bptr + kt * 16 + k0);
            Bs[k0 + 0][lr] = bv.x; Bs[k0 + 1][lr] = bv.y;
            Bs[k0 + 2][lr] = bv.z; Bs[k0 + 3][lr] = bv.w;
        }
        __syncthreads();
#pragma unroll
        for (int k = 0; k < 16; k++) {
            float a[8], b[8];
            *(float4*)&a[0] = *(float4*)&As[k][ty * 4];
            *(float4*)&a[4] = *(float4*)&As[k][64 + ty * 4];
            *(float4*)&b[0] = *(float4*)&Bs[k][tx * 4];
            *(float4*)&b[4] = *(float4*)&Bs[k][64 + tx * 4];
#pragma unroll
            for (int i = 0; i < 8; i++)
#pragma unroll
                for (int j = 0; j < 8; j++) acc[i][j] += a[i] * b[j];
        }
    }

#pragma unroll
    for (int rs = 0; rs < 2; rs++)
#pragma unroll
        for (int i = 0; i < 4; i++) {
            const int row = m0 + rs * 64 + ty * 4 + i;
            float* crow = g_qkv + ((size_t)o * MM + row) * QKVN;
#pragma unroll
            for (int cs = 0; cs < 2; cs++) {
                const int col = n0 + cs * 64 + tx * 4;
                float4 bv = *(const float4*)(bias + (size_t)o * QKVN + col);
                float4 w;
                w.x = acc[rs * 4 + i][cs * 4 + 0] + bv.x;
                w.y = acc[rs * 4 + i][cs * 4 + 1] + bv.y;
                w.z = acc[rs * 4 + i][cs * 4 + 2] + bv.z;
                w.w = acc[rs * 4 + i][cs * 4 + 3] + bv.w;
                *(float4*)(crow + col) = w;
            }
        }
}

// ---------------------------------------------------------------------------
// Flash-style segment attention. One block = one (o,b,nseg,h) instance x one
// 64-row Q chunk. Streams K/V in 64-row tiles with online softmax.
// Q/K staged d-major (GEMM layout), V s-major, P staged through padded smem.
// ---------------------------------------------------------------------------
#define ATTN_SMEM_FLOATS (4096 + 4096 + 64 * 68 + 64 * 68)   // 16896
#define ATTN_SMEM_BYTES  (ATTN_SMEM_FLOATS * 4)              // 67584

__global__ __launch_bounds__(256)
void attention_kernel()
{
    extern __shared__ float sm[];
    float* Qs = sm;                       // [d][q]  64x64
    float* Ks = sm + 4096;                // [d][s]  64x64
    float* Vs = sm + 8192;                // [s][d]  64x68 (padded)
    float* Ps = sm + 8192 + 64 * 68;      // [q][s]  64x68 (padded)

    const int t  = threadIdx.x;
    const int ty = t >> 4, tx = t & 15;
    const int qc = blockIdx.x;            // q chunk (0..7)
    const int n  = blockIdx.y / HH;       // segment
    const int h  = blockIdx.y % HH;       // head
    const int o  = blockIdx.z >> 1;       // offset
    const int bI = blockIdx.z & 1;        // batch

    const size_t base_m = (size_t)o * MM + (size_t)bI * LL + (size_t)n * SEGL;
    const float* Qg = g_qkv + (base_m + qc * 64) * QKVN + h * HD;

    const int lr = t >> 2;   // 0..63
    const int kc = t & 3;

    // Load Q chunk, transposed to [d][q]
#pragma unroll
    for (int u = 0; u < 4; u++) {
        const int d0 = u * 16 + kc * 4;
        float4 v = *(const float4*)(Qg + (size_t)lr * QKVN + d0);
        Qs[(d0 + 0) * 64 + lr] = v.x;
        Qs[(d0 + 1) * 64 + lr] = v.y;
        Qs[(d0 + 2) * 64 + lr] = v.z;
        Qs[(d0 + 3) * 64 + lr] = v.w;
    }

    float mrow[4], lrow[4], accO[4][4];
#pragma unroll
    for (int i = 0; i < 4; i++) {
        mrow[i] = -CUDART_INF_F;
        lrow[i] = 0.f;
#pragma unroll
        for (int j = 0; j < 4; j++) accO[i][j] = 0.f;
    }

    for (int kt = 0; kt < SEGL / 64; kt++) {
        __syncthreads();   // prior tile's P@V done before overwriting K/V/P
        const float* Kg = g_qkv + (base_m + kt * 64) * QKVN + DD + h * HD;
        const float* Vg = g_qkv + (base_m + kt * 64) * QKVN + 2 * DD + h * HD;
#pragma unroll
        for (int u = 0; u < 4; u++) {
            const int d0 = u * 16 + kc * 4;
            float4 v = *(const float4*)(Kg + (size_t)lr * QKVN + d0);
            Ks[(d0 + 0) * 64 + lr] = v.x;
            Ks[(d0 + 1) * 64 + lr] = v.y;
            Ks[(d0 + 2) * 64 + lr] = v.z;
            Ks[(d0 + 3) * 64 + lr] = v.w;
            float4 w = *(const float4*)(Vg + (size_t)lr * QKVN + d0);
            *(float4*)&Vs[lr * 68 + d0] = w;
        }
        __syncthreads();

        // S = Q @ K^T (64x64), register microtile 4x4
        float accS[4][4];
#pragma unroll
        for (int i = 0; i < 4; i++)
#pragma unroll
            for (int j = 0; j < 4; j++) accS[i][j] = 0.f;
#pragma unroll 16
        for (int d = 0; d < 64; d++) {
            float4 a = *(float4*)&Qs[d * 64 + ty * 4];
            float4 c = *(float4*)&Ks[d * 64 + tx * 4];
            accS[0][0] += a.x * c.x; accS[0][1] += a.x * c.y;
            accS[0][2] += a.x * c.z; accS[0][3] += a.x * c.w;
            accS[1][0] += a.y * c.x; accS[1][1] += a.y * c.y;
            accS[1][2] += a.y * c.z; accS[1][3] += a.y * c.w;
            accS[2][0] += a.z * c.x; accS[2][1] += a.z * c.y;
            accS[2][2] += a.z * c.z; accS[2][3] += a.z * c.w;
            accS[3][0] += a.w * c.x; accS[3][1] += a.w * c.y;
            accS[3][2] += a.w * c.z; accS[3][3] += a.w * c.w;
        }

        // Online softmax across the 16-lane tx group
#pragma unroll
        for (int i = 0; i < 4; i++) {
#pragma unroll
            for (int j = 0; j < 4; j++) accS[i][j] *= SCALE;
            float mx = fmaxf(fmaxf(accS[i][0], accS[i][1]),
                             fmaxf(accS[i][2], accS[i][3]));
#pragma unroll
            for (int off = 8; off > 0; off >>= 1)
                mx = fmaxf(mx, __shfl_xor_sync(0xffffffffu, mx, off));
            const float mnew  = fmaxf(mrow[i], mx);
            const float alpha = __expf(mrow[i] - mnew);
            mrow[i] = mnew;
            float rs = 0.f;
#pragma unroll
            for (int j = 0; j < 4; j++) {
                const float p = __expf(accS[i][j] - mnew);
                accS[i][j] = p;
                rs += p;
            }
#pragma unroll
            for (int off = 8; off > 0; off >>= 1)
                rs += __shfl_xor_sync(0xffffffffu, rs, off);
            lrow[i] = lrow[i] * alpha + rs;
#pragma unroll
            for (int j = 0; j < 4; j++) accO[i][j] *= alpha;
            *(float4*)&Ps[(ty * 4 + i) * 68 + tx * 4] =
                make_float4(accS[i][0], accS[i][1], accS[i][2], accS[i][3]);
        }
        __syncthreads();

        // accO += P @ V   (k = s, 64 steps)
#pragma unroll 16
        for (int s = 0; s < 64; s++) {
            float4 v = *(float4*)&Vs[s * 68 + tx * 4];
            const float p0 = Ps[(ty * 4 + 0) * 68 + s];
            const float p1 = Ps[(ty * 4 + 1) * 68 + s];
            const float p2 = Ps[(ty * 4 + 2) * 68 + s];
            const float p3 = Ps[(ty * 4 + 3) * 68 + s];
            accO[0][0] += p0 * v.x; accO[0][1] += p0 * v.y;
            accO[0][2] += p0 * v.z; accO[0][3] += p0 * v.w;
            accO[1][0] += p1 * v.x; accO[1][1] += p1 * v.y;
            accO[1][2] += p1 * v.z; accO[1][3] += p1 * v.w;
            accO[2][0] += p2 * v.x; accO[2][1] += p2 * v.y;
            accO[2][2] += p2 * v.z; accO[2][3] += p2 * v.w;
            accO[3][0] += p3 * v.x; accO[3][1] += p3 * v.y;
            accO[3][2] += p3 * v.z; accO[3][3] += p3 * v.w;
        }
    }

    // Normalize and write ctx[o][m][h*64 + d]
#pragma unroll
    for (int i = 0; i < 4; i++) {
        const float inv = 1.f / lrow[i];
        const size_t crow = base_m + qc * 64 + ty * 4 + i;
        float4 w = make_float4(accO[i][0] * inv, accO[i][1] * inv,
                               accO[i][2] * inv, accO[i][3] * inv);
        *(float4*)&g_ctx[crow * DD + h * HD + tx * 4] = w;
    }
}

// ---------------------------------------------------------------------------
// Output projection (same SGEMM structure) + dilated scatter into d_out.
// out[b, l*R+o, o*D + n] = ctx[o][b*L+l] . Wout[o][n] + bout[o][n]
// ---------------------------------------------------------------------------
__global__ __launch_bounds__(256, 2)
void proj_gemm_kernel(const float* __restrict__ W,
                      const float* __restrict__ bias,
                      float* __restrict__ out)
{
    __shared__ float As[16][128];
    __shared__ float Bs[16][128];

    const int o  = blockIdx.z;
    const int m0 = blockIdx.y * 128;
    const int n0 = blockIdx.x * 128;
    const int t  = threadIdx.x;
    const int ty = t >> 4, tx = t & 15;

    const int lr = t >> 1;
    const int kc = t & 1;

    const float* aptr = g_ctx + ((size_t)o * MM + (m0 + lr)) * DD;
    const float* bptr = W + ((size_t)o * DD + (n0 + lr)) * DD;

    float acc[8][8];
#pragma unroll
    for (int i = 0; i < 8; i++)
#pragma unroll
        for (int j = 0; j < 8; j++) acc[i][j] = 0.f;

    for (int kt = 0; kt < DD / 16; kt++) {
        __syncthreads();
#pragma unroll
        for (int u = 0; u < 2; u++) {
            const int k0 = (kc + 2 * u) * 4;
            float4 av = *(const float4*)(aptr + kt * 16 + k0);
            As[k0 + 0][lr] = av.x; As[k0 + 1][lr] = av.y;
            As[k0 + 2][lr] = av.z; As[k0 + 3][lr] = av.w;
            float4 bv = *(const float4*)(bptr + kt * 16 + k0);
            Bs[k0 + 0][lr] = bv.x; Bs[k0 + 1][lr] = bv.y;
            Bs[k0 + 2][lr] = bv.z; Bs[k0 + 3][lr] = bv.w;
        }
        __syncthreads();
#pragma unroll
        for (int k = 0; k < 16; k++) {
            float a[8], b[8];
            *(float4*)&a[0] = *(float4*)&As[k][ty * 4];
            *(float4*)&a[4] = *(float4*)&As[k][64 + ty * 4];
            *(float4*)&b[0] = *(float4*)&Bs[k][tx * 4];
            *(float4*)&b[4] = *(float4*)&Bs[k][64 + tx * 4];
#pragma unroll
            for (int i = 0; i < 8; i++)
#pragma unroll
                for (int j = 0; j < 8; j++) acc[i][j] += a[i] * b[j];
        }
    }

#pragma unroll
    for (int rs = 0; rs < 2; rs++)
#pragma unroll
        for (int i = 0; i < 4; i++) {
            const int row = m0 + rs * 64 + ty * 4 + i;
            const int bI = row >> 11;
            const int l  = row & 2047;
            const int s  = l * RR + o;
            float* orow = out + ((size_t)bI * SS + s) * (RR * DD) + o * DD;
#pragma unroll
            for (int cs = 0; cs < 2; cs++) {
                const int col = n0 + cs * 64 + tx * 4;
                float4 bv = *(const float4*)(bias + (size_t)o * DD + col);
                float4 w;
                w.x = acc[rs * 4 + i][cs * 4 + 0] + bv.x;
                w.y = acc[rs * 4 + i][cs * 4 + 1] + bv.y;
                w.z = acc[rs * 4 + i][cs * 4 + 2] + bv.z;
                w.w = acc[rs * 4 + i][cs * 4 + 3] + bv.w;
                *(float4*)(orow + col) = w;
            }
        }
}

// ---------------------------------------------------------------------------
extern "C" void kernel_launch(void* const* d_in, const int* in_sizes, int n_in,
                              void* d_out, int out_size)
{
    const float* x    = (const float*)d_in[0];
    const float* Wqkv = (const float*)d_in[1];
    const float* bqkv = (const float*)d_in[2];
    const float* Wout = (const float*)d_in[3];
    const float* bout = (const float*)d_in[4];
    float* out = (float*)d_out;

    // Output is 75% structural zeros: zero everything, then scatter real rows.
    cudaMemsetAsync(out, 0, (size_t)out_size * sizeof(float));

    qkv_gemm_kernel<<<dim3(QKVN / 128, MM / 128, RR), 256>>>(x, Wqkv, bqkv);

    cudaFuncSetAttribute(attention_kernel,
                         cudaFuncAttributeMaxDynamicSharedMemorySize,
                         ATTN_SMEM_BYTES);
    attention_kernel<<<dim3(SEGL / 64, NSEG * HH, RR * BB), 256,
                       ATTN_SMEM_BYTES>>>();

    proj_gemm_kernel<<<dim3(DD / 128, MM / 128, RR), 256>>>(Wout, bout, out);
}